// round 15
// baseline (speedup 1.0000x reference)
#include <cuda_runtime.h>
#include <cstdint>

#define S_TOT  2560
#define S_TXTC 512
#define S_IMGC 2048
#define DIMK   3072
#define NHEADS 24
#define HDIM   128
#define E3     9216
#define EPSV   1e-6f
#define QSCALE 0.088388347648318447f   // 1/sqrt(128)
#define LOG2E  1.4426950408889634f

// ---------------- scratch ---------------------------------------------------
static __device__ float g_Q[NHEADS * S_TOT * HDIM];         // rounded, *log2e
static __device__ float g_K[NHEADS * S_TOT * HDIM];
static __device__ float g_Vt[NHEADS * HDIM * S_TOT];        // [h][d][s]
static __device__ float g_O[S_TOT * DIMK];
static __device__ float g_Wq[E3 * DIMK];
static __device__ float g_Wa[E3 * DIMK];
static __device__ float g_Wo[DIMK * DIMK];
static __device__ float g_Wao[DIMK * DIMK];
static __device__ float g_X[S_TOT * DIMK];

// ---------------- helpers ---------------------------------------------------
__device__ __forceinline__ unsigned f2tf(float x) {
    unsigned u;
    asm("cvt.rna.tf32.f32 %0, %1;" : "=r"(u) : "f"(x));
    return u;
}
__device__ __forceinline__ float rtf(float x) { return __uint_as_float(f2tf(x)); }
__device__ __forceinline__ float ex2(float x) {
    float r;
    asm("ex2.approx.f32 %0, %1;" : "=f"(r) : "f"(x));
    return r;
}
__device__ __forceinline__ uint32_t smem_u32(const void* p) {
    uint32_t a;
    asm("{ .reg .u64 t; cvta.to.shared.u64 t, %1; cvt.u32.u64 %0, t; }"
        : "=r"(a) : "l"(p));
    return a;
}
__device__ __forceinline__ void mma8(float (&d)[4], const unsigned (&a)[4],
                                     const unsigned (&b)[2]) {
    asm volatile(
        "mma.sync.aligned.m16n8k8.row.col.f32.tf32.tf32.f32 "
        "{%0,%1,%2,%3}, {%4,%5,%6,%7}, {%8,%9}, {%0,%1,%2,%3};\n"
        : "+f"(d[0]), "+f"(d[1]), "+f"(d[2]), "+f"(d[3])
        : "r"(a[0]), "r"(a[1]), "r"(a[2]), "r"(a[3]), "r"(b[0]), "r"(b[1]));
}
#define LDSM4(r0, r1, r2, r3, addr)                                            \
    asm volatile("ldmatrix.sync.aligned.m8n8.x4.shared.b16 {%0,%1,%2,%3}, [%4];" \
                 : "=r"(r0), "=r"(r1), "=r"(r2), "=r"(r3) : "r"(addr))
#define STS32(addr, x)                                                         \
    asm volatile("st.shared.b32 [%0], %1;" :: "r"(addr), "r"(x) : "memory")
__device__ __forceinline__ void cp16(uint32_t s, const void* g) {
    asm volatile("cp.async.cg.shared.global [%0], [%1], 16;" :: "r"(s), "l"(g));
}
#define CP_COMMIT() asm volatile("cp.async.commit_group;" ::: "memory")
#define CP_WAIT2()  asm volatile("cp.async.wait_group 2;" ::: "memory")
#define CP_WAIT1()  asm volatile("cp.async.wait_group 1;" ::: "memory")
#define CP_WAIT0()  asm volatile("cp.async.wait_group 0;" ::: "memory")

// ---------------- kernel 0: fused tf32 pre-round ----------------------------
#define N_WQ4  (E3 * DIMK / 4)
#define N_WO4  (DIMK * DIMK / 4)
#define N_ENC4 (S_TXTC * DIMK / 4)
#define N_HID4 (S_IMGC * DIMK / 4)
#define N_TOT4 (2 * N_WQ4 + 2 * N_WO4 + N_ENC4 + N_HID4)

__global__ void cvt_all_kernel(const float* __restrict__ w_qkv,
                               const float* __restrict__ w_add,
                               const float* __restrict__ w_out,
                               const float* __restrict__ w_add_out,
                               const float* __restrict__ enc,
                               const float* __restrict__ hid)
{
    for (int i = blockIdx.x * blockDim.x + threadIdx.x; i < N_TOT4;
         i += gridDim.x * blockDim.x) {
        const float4* s;
        float4* d;
        int off = i;
        if (off < N_WQ4) { s = (const float4*)w_qkv; d = (float4*)g_Wq; }
        else if ((off -= N_WQ4) < N_WQ4) { s = (const float4*)w_add; d = (float4*)g_Wa; }
        else if ((off -= N_WQ4) < N_WO4) { s = (const float4*)w_out; d = (float4*)g_Wo; }
        else if ((off -= N_WO4) < N_WO4) { s = (const float4*)w_add_out; d = (float4*)g_Wao; }
        else if ((off -= N_WO4) < N_ENC4) { s = (const float4*)enc; d = (float4*)g_X; }
        else { off -= N_ENC4; s = (const float4*)hid;
               d = (float4*)(g_X + (size_t)S_TXTC * DIMK); }
        float4 v = s[off];
        v.x = rtf(v.x); v.y = rtf(v.y); v.z = rtf(v.z); v.w = rtf(v.w);
        d[off] = v;
    }
}

// =================== GEMM: 128x256 tile, BK=32, cp.async 4-stage ============
#define AST_B 16384
#define BST_B 32768
#define GEMM_SMEM_BYTES (4 * AST_B + 4 * BST_B)   // 196608

__device__ __forceinline__ void gemm_issue_stage(
    const float* __restrict__ A, const float* __restrict__ W,
    uint32_t su, int slot, int kk, int t)
{
    const uint32_t sA = su + slot * AST_B;
    const uint32_t sB = su + 4 * AST_B + slot * BST_B;
#pragma unroll
    for (int l = 0; l < 4; l++) {
        int idx = t + l * 256;
        int row = idx >> 3, c = idx & 7;
        cp16(sA + row * 128 + ((c ^ (row & 7)) << 4),
             A + (size_t)row * DIMK + kk + c * 4);
    }
#pragma unroll
    for (int l = 0; l < 8; l++) {
        int idx = t + l * 256;
        int row = idx >> 3, c = idx & 7;
        cp16(sB + row * 128 + ((c ^ (row & 7)) << 4),
             W + (size_t)row * DIMK + kk + c * 4);
    }
    CP_COMMIT();
}

__device__ __forceinline__ void gemm_tf32_main(
    const float* __restrict__ A, const float* __restrict__ W,
    uint32_t su, float (&acc)[4][8][4], int t)
{
    const int lane = t & 31, wid = t >> 5;
    const int wm = wid >> 2, wn = wid & 3;
    const int arow = (lane & 7) + ((lane >> 3) & 1) * 8;
    const int asel = lane >> 4;
    const int brow = (lane & 7) + ((lane >> 4) & 1) * 8;
    const int bsel = (lane >> 3) & 1;

    gemm_issue_stage(A, W, su, 0, 0, t);
    gemm_issue_stage(A, W, su, 1, 32, t);
    gemm_issue_stage(A, W, su, 2, 64, t);

    const int NST = DIMK / 32;   // 96
    for (int i = 0; i < NST; i++) {
        if (i < NST - 2) CP_WAIT2();
        else if (i == NST - 2) CP_WAIT1();
        else CP_WAIT0();
        __syncthreads();
        if (i + 3 < NST)
            gemm_issue_stage(A, W, su, (i + 3) & 3, (i + 3) * 32, t);

        const int slot = i & 3;
        const uint32_t cA = su + slot * AST_B;
        const uint32_t cB = su + 4 * AST_B + slot * BST_B;
#pragma unroll
        for (int ks = 0; ks < 4; ks++) {
            unsigned af[4][4], bf[8][2];
#pragma unroll
            for (int mt = 0; mt < 4; mt++) {
                int r = wm * 64 + mt * 16 + arow;
                int c = ks * 2 + asel;
                LDSM4(af[mt][0], af[mt][1], af[mt][2], af[mt][3],
                      cA + r * 128 + ((c ^ (r & 7)) << 4));
            }
#pragma unroll
            for (int p = 0; p < 4; p++) {
                int r = wn * 64 + p * 16 + brow;
                int c = ks * 2 + bsel;
                LDSM4(bf[2 * p][0], bf[2 * p][1], bf[2 * p + 1][0],
                      bf[2 * p + 1][1], cB + r * 128 + ((c ^ (r & 7)) << 4));
            }
#pragma unroll
            for (int mt = 0; mt < 4; mt++)
#pragma unroll
                for (int nt = 0; nt < 8; nt++)
                    mma8(acc[mt][nt], af[mt], bf[nt]);
        }
    }
}

// ------- kernel 1: QKV projection + fused RMSNorm/RoPE/V-transpose ----------
__global__ __launch_bounds__(256, 1) void gemm_qkv_kernel(
    const float* __restrict__ b_img, const float* __restrict__ b_txt,
    const float* __restrict__ cosT, const float* __restrict__ sinT,
    const float* __restrict__ nq,  const float* __restrict__ nk,
    const float* __restrict__ naq, const float* __restrict__ nak)
{
    extern __shared__ unsigned gsm[];
    const uint32_t su = smem_u32(gsm);
    const int m0 = blockIdx.x * 128;
    const int n0 = blockIdx.y * 256;
    const bool txt = (m0 < S_TXTC);
    const float* A    = g_X + (size_t)m0 * DIMK;
    const float* W    = (txt ? g_Wa : g_Wq) + (size_t)n0 * DIMK;
    const float* bias = txt ? b_txt : b_img;

    const int t = threadIdx.x;
    float acc[4][8][4];
#pragma unroll
    for (int i = 0; i < 4; i++)
#pragma unroll
        for (int j = 0; j < 8; j++)
#pragma unroll
            for (int c = 0; c < 4; c++) acc[i][j][c] = 0.f;

    gemm_tf32_main(A, W, su, acc, t);

    const int lane = t & 31, wid = t >> 5;
    const int g = lane >> 2, t4 = lane & 3;
    const int wm = wid >> 2, wn = wid & 3;

#pragma unroll
    for (int mt = 0; mt < 4; mt++)
#pragma unroll
        for (int nt = 0; nt < 8; nt++) {
            int c = n0 + wn * 64 + nt * 8 + t4 * 2;
            acc[mt][nt][0] += bias[c];     acc[mt][nt][1] += bias[c + 1];
            acc[mt][nt][2] += bias[c];     acc[mt][nt][3] += bias[c + 1];
        }

    const int sec = n0 / DIMK;            // 0=Q 1=K 2=V
    const int ncol0 = n0 - sec * DIMK;
    __syncthreads();

    if (sec < 2) {
        float* sums = (float*)gsm;
#pragma unroll
        for (int mt = 0; mt < 4; mt++) {
            float p0 = 0.f, p1 = 0.f;
#pragma unroll
            for (int nt = 0; nt < 8; nt++) {
                p0 += acc[mt][nt][0] * acc[mt][nt][0]
                    + acc[mt][nt][1] * acc[mt][nt][1];
                p1 += acc[mt][nt][2] * acc[mt][nt][2]
                    + acc[mt][nt][3] * acc[mt][nt][3];
            }
            p0 += __shfl_xor_sync(0xffffffffu, p0, 1);
            p0 += __shfl_xor_sync(0xffffffffu, p0, 2);
            p1 += __shfl_xor_sync(0xffffffffu, p1, 1);
            p1 += __shfl_xor_sync(0xffffffffu, p1, 2);
            if (t4 == 0) {
                int r = wm * 64 + mt * 16 + g;
                sums[wn * 128 + r] = p0;
                sums[wn * 128 + r + 8] = p1;
            }
        }
        __syncthreads();

        const float* wsel = (sec == 0) ? (txt ? naq : nq) : (txt ? nak : nk);
        float* dstb = (sec == 0) ? g_Q : g_K;
        const float oscale = (sec == 0) ? (QSCALE * LOG2E) : 1.0f;
        const int h = ncol0 / 128 + (wn >> 1);
        const int dbase = (wn & 1) * 64;

#pragma unroll
        for (int mt = 0; mt < 4; mt++) {
            int r0 = wm * 64 + mt * 16 + g;
            float tot0 = sums[wn * 128 + r0] + sums[(wn ^ 1) * 128 + r0];
            float tot1 = sums[wn * 128 + r0 + 8] + sums[(wn ^ 1) * 128 + r0 + 8];
            float rs0 = rsqrtf(tot0 * (1.0f / HDIM) + EPSV);
            float rs1 = rsqrtf(tot1 * (1.0f / HDIM) + EPSV);
            int s0 = m0 + r0, s1 = s0 + 8;
            float* d0 = dstb + ((size_t)h * S_TOT + s0) * HDIM + dbase;
            float* d1 = dstb + ((size_t)h * S_TOT + s1) * HDIM + dbase;
#pragma unroll
            for (int nt = 0; nt < 8; nt++) {
                int d = dbase + nt * 8 + t4 * 2;
                float w0 = wsel[d], w1 = wsel[d + 1];
                int i = d >> 1;
                float c0 = cosT[s0 * 64 + i], n0r = sinT[s0 * 64 + i];
                float c1 = cosT[s1 * 64 + i], n1r = sinT[s1 * 64 + i];
                float a0 = acc[mt][nt][0] * rs0 * w0;
                float a1 = acc[mt][nt][1] * rs0 * w1;
                float b0 = acc[mt][nt][2] * rs1 * w0;
                float b1 = acc[mt][nt][3] * rs1 * w1;
                float2 v0 = make_float2(rtf((a0 * c0 - a1 * n0r) * oscale),
                                        rtf((a1 * c0 + a0 * n0r) * oscale));
                float2 v1 = make_float2(rtf((b0 * c1 - b1 * n1r) * oscale),
                                        rtf((b1 * c1 + b0 * n1r) * oscale));
                *(float2*)(d0 + nt * 8 + t4 * 2) = v0;
                *(float2*)(d1 + nt * 8 + t4 * 2) = v1;
            }
        }
    } else {
        float* vsm = (float*)gsm;
#pragma unroll
        for (int mt = 0; mt < 4; mt++) {
            int r0 = wm * 64 + mt * 16 + g;
#pragma unroll
            for (int nt = 0; nt < 8; nt++) {
                int col = wn * 64 + nt * 8 + t4 * 2;
                vsm[col * 132 + r0]           = rtf(acc[mt][nt][0]);
                vsm[(col + 1) * 132 + r0]     = rtf(acc[mt][nt][1]);
                vsm[col * 132 + r0 + 8]       = rtf(acc[mt][nt][2]);
                vsm[(col + 1) * 132 + r0 + 8] = rtf(acc[mt][nt][3]);
            }
        }
        __syncthreads();
        const int h0 = ncol0 / 128;
#pragma unroll
        for (int pass = 0; pass < 8; pass++) {
            int dcol = pass * 32 + (t >> 3);
            int sb = (t & 7) * 16;
            int h = h0 + (dcol >> 7);
            int dd = dcol & 127;
            float* dst = g_Vt + ((size_t)h * HDIM + dd) * S_TOT + m0 + sb;
            const float* srcr = vsm + dcol * 132 + sb;
#pragma unroll
            for (int j = 0; j < 16; j += 4)
                *(float4*)(dst + j) = make_float4(srcr[j], srcr[j + 1],
                                                  srcr[j + 2], srcr[j + 3]);
        }
    }
}

// ---------------- kernel 4: output projections + scatter --------------------
__global__ __launch_bounds__(256, 1) void gemm_out_kernel(
    const float* __restrict__ b_img, const float* __restrict__ b_txt,
    float* __restrict__ out)
{
    extern __shared__ unsigned gsm[];
    const uint32_t su = smem_u32(gsm);
    const int m0 = blockIdx.x * 128;
    const int n0 = blockIdx.y * 256;
    const bool txt = (m0 < S_TXTC);
    const float* A    = g_O + (size_t)m0 * DIMK;
    const float* W    = (txt ? g_Wao : g_Wo) + (size_t)n0 * DIMK;
    const float* bias = txt ? b_txt : b_img;

    const int t = threadIdx.x;
    float acc[4][8][4];
#pragma unroll
    for (int i = 0; i < 4; i++)
#pragma unroll
        for (int j = 0; j < 8; j++)
#pragma unroll
            for (int c = 0; c < 4; c++) acc[i][j][c] = 0.f;

    gemm_tf32_main(A, W, su, acc, t);

    const int lane = t & 31, wid = t >> 5;
    const int g = lane >> 2, t4 = lane & 3;
    const int wm = wid >> 2, wn = wid & 3;
#pragma unroll
    for (int mt = 0; mt < 4; mt++) {
        int s = m0 + wm * 64 + mt * 16 + g;
        int orow0 = txt ? (S_IMGC + s) : (s - S_TXTC);
        int orow1 = orow0 + 8;
#pragma unroll
        for (int nt = 0; nt < 8; nt++) {
            int c = n0 + wn * 64 + nt * 8 + t4 * 2;
            float2 v0 = make_float2(acc[mt][nt][0] + bias[c],
                                    acc[mt][nt][1] + bias[c + 1]);
            float2 v1 = make_float2(acc[mt][nt][2] + bias[c],
                                    acc[mt][nt][3] + bias[c + 1]);
            *(float2*)(out + (size_t)orow0 * DIMK + c) = v0;
            *(float2*)(out + (size_t)orow1 * DIMK + c) = v1;
        }
    }
}

// ====== flash v7: Q in smem (low regs), single-buffer K, dbl-buffer V =======
#define QS_B   65536                    // 128 x 128 f32, 512B rows, XOR swizzle
#define KS_B   33792                    // 64 x 132 f32
#define VT_B   34816                    // 128 x 68 f32
#define F_K_OFF  QS_B                   // 65536
#define F_V_OFF  (QS_B + KS_B)          // 99328
#define F_P_OFF  (F_V_OFF + 2 * VT_B)   // 168960
#define FLASH_SMEM_BYTES (F_P_OFF + VT_B)   // 203776

__device__ __forceinline__ void flash_issue_k(const float* __restrict__ Kg,
                                              uint32_t ksb, int t)
{
#pragma unroll
    for (int l = 0; l < 8; l++) {
        int idx = t + l * 256;
        int r = idx >> 5, c = idx & 31;
        cp16(ksb + (uint32_t)(r * 528 + c * 16), Kg + (size_t)r * HDIM + c * 4);
    }
}
__device__ __forceinline__ void flash_issue_v(const float* __restrict__ Vt,
                                              uint32_t vtb, int t)
{
#pragma unroll
    for (int l = 0; l < 8; l++) {
        int idx = t + l * 256;
        int r = idx >> 4, c = idx & 15;
        cp16(vtb + (uint32_t)(r * 272 + c * 16), Vt + (size_t)r * S_TOT + c * 4);
    }
}

__global__ __launch_bounds__(256, 1) void flash_v7_kernel()
{
    extern __shared__ unsigned fsm[];
    const uint32_t su = smem_u32(fsm);

    const int qt = blockIdx.x, h = blockIdx.y;
    const int t = threadIdx.x, lane = t & 31, wid = t >> 5;
    const float* Kg0 = g_K + (size_t)h * S_TOT * HDIM;
    const float* Vt0 = g_Vt + (size_t)h * HDIM * S_TOT;

    const int g = lane >> 2, t4 = lane & 3;
    const int qb = wid * 16;

    // fragment addressing
    const int arow = (lane & 7) + ((lane >> 3) & 1) * 8;   // A-frag rows
    const int asel = lane >> 4;
    const int brow = (lane & 7) + ((lane >> 4) & 1) * 8;   // B-frag rows
    const int bcol = ((lane >> 3) & 1) * 4;
    const int parow = (lane & 7) + ((lane >> 3) & 1) * 8;
    const int pacol = (lane >> 4) * 4;
    uint32_t okk[4], ovv[8], opa;
#pragma unroll
    for (int p = 0; p < 4; p++) okk[p] = (uint32_t)((p * 16 + brow) * 132 + bcol) * 4;
#pragma unroll
    for (int p = 0; p < 8; p++) ovv[p] = (uint32_t)((p * 16 + brow) * 68 + bcol) * 4;
    opa = (uint32_t)((qb + parow) * 68 + pacol) * 4;
    const int qrow = qb + arow;                            // Q smem row
    const uint32_t qrb = su + (uint32_t)qrow * 512;

    // ---- prologue: Q tile + K0 + V0
    const float* Qg = g_Q + ((size_t)h * S_TOT + qt * 128) * HDIM;
#pragma unroll
    for (int l = 0; l < 16; l++) {
        int idx = t + l * 256;
        int r = idx >> 5, c = idx & 31;          // 128 rows x 32 chunks
        cp16(su + (uint32_t)(r * 512 + ((c ^ (r & 7)) << 4)),
             Qg + (size_t)r * HDIM + c * 4);
    }
    flash_issue_k(Kg0, su + F_K_OFF, t);
    flash_issue_v(Vt0, su + F_V_OFF, t);
    CP_COMMIT();

    float o[16][4];
#pragma unroll
    for (int dt = 0; dt < 16; dt++)
#pragma unroll
        for (int c = 0; c < 4; c++) o[dt][c] = 0.f;
    float mrow[2] = {-1e30f, -1e30f}, lrow[2] = {0.f, 0.f};

    CP_WAIT0();
    __syncthreads();

    const uint32_t ksb = su + F_K_OFF;
    const uint32_t psb = su + F_P_OFF;
    const int NT = S_TOT / 64;   // 40
    for (int kt = 0; kt < NT; kt++) {
        const int b = kt & 1;

        // ---- S = Q K^T (Q from smem A-frags, K single buffer)
        float sc[8][4];
#pragma unroll
        for (int nt = 0; nt < 8; nt++)
#pragma unroll
            for (int c = 0; c < 4; c++) sc[nt][c] = 0.f;
#pragma unroll
        for (int ks = 0; ks < 16; ks++) {
            unsigned af[4];
            int qc = ks * 2 + asel;
            LDSM4(af[0], af[1], af[2], af[3],
                  qrb + ((uint32_t)(qc ^ (qrow & 7)) << 4));
            unsigned bf[8][2];
#pragma unroll
            for (int p = 0; p < 4; p++)
                LDSM4(bf[2 * p][0], bf[2 * p][1], bf[2 * p + 1][0],
                      bf[2 * p + 1][1], ksb + okk[p] + ks * 32);
#pragma unroll
            for (int nt = 0; nt < 8; nt++)
                mma8(sc[nt], af, bf[nt]);
        }
        __syncthreads();   // all warps done reading Ks -> safe to refill

        if (kt + 1 < NT) {
            flash_issue_k(Kg0 + (size_t)(kt + 1) * 64 * HDIM, ksb, t);
            flash_issue_v(Vt0 + (size_t)(kt + 1) * 64,
                          su + F_V_OFF + (b ^ 1) * VT_B, t);
            CP_COMMIT();
        }

        // ---- online softmax (log2 domain)
        float mx0 = -1e30f, mx1 = -1e30f;
#pragma unroll
        for (int nt = 0; nt < 8; nt++) {
            mx0 = fmaxf(mx0, fmaxf(sc[nt][0], sc[nt][1]));
            mx1 = fmaxf(mx1, fmaxf(sc[nt][2], sc[nt][3]));
        }
        mx0 = fmaxf(mx0, __shfl_xor_sync(0xffffffffu, mx0, 1));
        mx0 = fmaxf(mx0, __shfl_xor_sync(0xffffffffu, mx0, 2));
        mx1 = fmaxf(mx1, __shfl_xor_sync(0xffffffffu, mx1, 1));
        mx1 = fmaxf(mx1, __shfl_xor_sync(0xffffffffu, mx1, 2));
        float m0n = fmaxf(mrow[0], mx0), m1n = fmaxf(mrow[1], mx1);
        float a0 = ex2(mrow[0] - m0n), a1 = ex2(mrow[1] - m1n);
        mrow[0] = m0n; mrow[1] = m1n;

        float rs0 = 0.f, rs1 = 0.f;
#pragma unroll
        for (int nt = 0; nt < 8; nt++) {
            sc[nt][0] = ex2(sc[nt][0] - m0n);
            sc[nt][1] = ex2(sc[nt][1] - m0n);
            sc[nt][2] = ex2(sc[nt][2] - m1n);
            sc[nt][3] = ex2(sc[nt][3] - m1n);
            rs0 += sc[nt][0] + sc[nt][1];
            rs1 += sc[nt][2] + sc[nt][3];
        }
        rs0 += __shfl_xor_sync(0xffffffffu, rs0, 1);
        rs0 += __shfl_xor_sync(0xffffffffu, rs0, 2);
        rs1 += __shfl_xor_sync(0xffffffffu, rs1, 1);
        rs1 += __shfl_xor_sync(0xffffffffu, rs1, 2);
        lrow[0] = lrow[0] * a0 + rs0;
        lrow[1] = lrow[1] * a1 + rs1;

#pragma unroll
        for (int dt = 0; dt < 16; dt++) {
            o[dt][0] *= a0; o[dt][1] *= a0;
            o[dt][2] *= a1; o[dt][3] *= a1;
        }

        // ---- P -> smem (per-warp private rows)
#pragma unroll
        for (int nt = 0; nt < 8; nt++) {
            uint32_t pb = psb + (uint32_t)((qb + g) * 68 + nt * 8 + t4 * 2) * 4;
            STS32(pb,     f2tf(sc[nt][0]));
            STS32(pb + 4, f2tf(sc[nt][1]));
            STS32(pb + 8 * 68 * 4,     f2tf(sc[nt][2]));
            STS32(pb + 8 * 68 * 4 + 4, f2tf(sc[nt][3]));
        }
        __syncwarp();

        // ---- O += P V[kt]
        const uint32_t vtb = su + F_V_OFF + b * VT_B;
#pragma unroll
        for (int ks = 0; ks < 8; ks++) {
            unsigned pa[4];
            LDSM4(pa[0], pa[1], pa[2], pa[3], psb + opa + ks * 32);
#pragma unroll
            for (int p = 0; p < 8; p++) {
                unsigned vf0[2], vf1[2];
                LDSM4(vf0[0], vf0[1], vf1[0], vf1[1], vtb + ovv[p] + ks * 32);
                mma8(o[2 * p], pa, vf0);
                mma8(o[2 * p + 1], pa, vf1);
            }
        }

        if (kt + 1 < NT) CP_WAIT0();
        __syncthreads();   // K[kt+1]/V[kt+1] visible to all; P rows reusable
    }

    float inv0 = 1.0f / lrow[0], inv1 = 1.0f / lrow[1];
    int s0 = qt * 128 + qb + g;
    float* dst0 = g_O + (size_t)s0 * DIMK + h * HDIM;
    float* dst1 = dst0 + (size_t)8 * DIMK;
#pragma unroll
    for (int dt = 0; dt < 16; dt++) {
        int d = dt * 8 + t4 * 2;
        float2 w0 = make_float2(rtf(o[dt][0] * inv0), rtf(o[dt][1] * inv0));
        float2 w1 = make_float2(rtf(o[dt][2] * inv1), rtf(o[dt][3] * inv1));
        *(float2*)(dst0 + d) = w0;
        *(float2*)(dst1 + d) = w1;
    }
}

// ---------------- launch ----------------------------------------------------
extern "C" void kernel_launch(void* const* d_in, const int* in_sizes, int n_in,
                              void* d_out, int out_size)
{
    const float* hid       = (const float*)d_in[0];
    const float* enc       = (const float*)d_in[1];
    const float* cosT      = (const float*)d_in[2];
    const float* sinT      = (const float*)d_in[3];
    const float* w_qkv     = (const float*)d_in[4];
    const float* b_qkv     = (const float*)d_in[5];
    const float* w_add     = (const float*)d_in[6];
    const float* b_add     = (const float*)d_in[7];
    const float* nq        = (const float*)d_in[8];
    const float* nk        = (const float*)d_in[9];
    const float* naq       = (const float*)d_in[10];
    const float* nak       = (const float*)d_in[11];
    const float* w_out     = (const float*)d_in[12];
    const float* b_out     = (const float*)d_in[13];
    const float* w_add_out = (const float*)d_in[14];
    const float* b_add_out = (const float*)d_in[15];
    float* out = (float*)d_out;

    static bool attr_done = false;
    if (!attr_done) {
        cudaFuncSetAttribute(gemm_qkv_kernel,
            cudaFuncAttributeMaxDynamicSharedMemorySize, GEMM_SMEM_BYTES);
        cudaFuncSetAttribute(gemm_out_kernel,
            cudaFuncAttributeMaxDynamicSharedMemorySize, GEMM_SMEM_BYTES);
        cudaFuncSetAttribute(flash_v7_kernel,
            cudaFuncAttributeMaxDynamicSharedMemorySize, FLASH_SMEM_BYTES);
        attr_done = true;
    }

    cvt_all_kernel<<<2048, 256>>>(w_qkv, w_add, w_out, w_add_out, enc, hid);

    gemm_qkv_kernel<<<dim3(S_TOT / 128, E3 / 256), 256, GEMM_SMEM_BYTES>>>(
        b_qkv, b_add, cosT, sinT, nq, nk, naq, nak);

    flash_v7_kernel<<<dim3(S_TOT / 128, NHEADS), 256, FLASH_SMEM_BYTES>>>();

    gemm_out_kernel<<<dim3(S_TOT / 128, DIMK / 256), 256, GEMM_SMEM_BYTES>>>(
        b_out, b_add_out, out);
}

// round 16
// speedup vs baseline: 1.0315x; 1.0315x over previous
#include <cuda_runtime.h>
#include <cstdint>

#define S_TOT  2560
#define S_TXTC 512
#define S_IMGC 2048
#define DIMK   3072
#define NHEADS 24
#define HDIM   128
#define E3     9216
#define EPSV   1e-6f
#define QSCALE 0.088388347648318447f   // 1/sqrt(128)
#define LOG2E  1.4426950408889634f

// ---------------- scratch ---------------------------------------------------
static __device__ float g_Q[NHEADS * S_TOT * HDIM];         // rounded, *log2e
static __device__ float g_K[NHEADS * S_TOT * HDIM];
static __device__ float g_Vt[NHEADS * HDIM * S_TOT];        // [h][d][s]
static __device__ float g_O[S_TOT * DIMK];
static __device__ float g_Wq[E3 * DIMK];
static __device__ float g_Wa[E3 * DIMK];
static __device__ float g_Wo[DIMK * DIMK];
static __device__ float g_Wao[DIMK * DIMK];
static __device__ float g_X[S_TOT * DIMK];

// ---------------- helpers ---------------------------------------------------
__device__ __forceinline__ unsigned f2tf(float x) {
    unsigned u;
    asm("cvt.rna.tf32.f32 %0, %1;" : "=r"(u) : "f"(x));
    return u;
}
__device__ __forceinline__ float rtf(float x) { return __uint_as_float(f2tf(x)); }
__device__ __forceinline__ float ex2(float x) {
    float r;
    asm("ex2.approx.f32 %0, %1;" : "=f"(r) : "f"(x));
    return r;
}
__device__ __forceinline__ uint32_t smem_u32(const void* p) {
    uint32_t a;
    asm("{ .reg .u64 t; cvta.to.shared.u64 t, %1; cvt.u32.u64 %0, t; }"
        : "=r"(a) : "l"(p));
    return a;
}
__device__ __forceinline__ void mma8(float (&d)[4], const unsigned (&a)[4],
                                     const unsigned (&b)[2]) {
    asm volatile(
        "mma.sync.aligned.m16n8k8.row.col.f32.tf32.tf32.f32 "
        "{%0,%1,%2,%3}, {%4,%5,%6,%7}, {%8,%9}, {%0,%1,%2,%3};\n"
        : "+f"(d[0]), "+f"(d[1]), "+f"(d[2]), "+f"(d[3])
        : "r"(a[0]), "r"(a[1]), "r"(a[2]), "r"(a[3]), "r"(b[0]), "r"(b[1]));
}
#define LDSM4(r0, r1, r2, r3, addr)                                            \
    asm volatile("ldmatrix.sync.aligned.m8n8.x4.shared.b16 {%0,%1,%2,%3}, [%4];" \
                 : "=r"(r0), "=r"(r1), "=r"(r2), "=r"(r3) : "r"(addr))
#define STS32(addr, x)                                                         \
    asm volatile("st.shared.b32 [%0], %1;" :: "r"(addr), "r"(x) : "memory")
__device__ __forceinline__ void cp16(uint32_t s, const void* g) {
    asm volatile("cp.async.cg.shared.global [%0], [%1], 16;" :: "r"(s), "l"(g));
}
#define CP_COMMIT() asm volatile("cp.async.commit_group;" ::: "memory")
#define CP_WAIT2()  asm volatile("cp.async.wait_group 2;" ::: "memory")
#define CP_WAIT1()  asm volatile("cp.async.wait_group 1;" ::: "memory")
#define CP_WAIT0()  asm volatile("cp.async.wait_group 0;" ::: "memory")

// ---------------- kernel 0: fused tf32 pre-round (x2 ILP) -------------------
#define N_WQ4  (E3 * DIMK / 4)
#define N_WO4  (DIMK * DIMK / 4)
#define N_ENC4 (S_TXTC * DIMK / 4)
#define N_HID4 (S_IMGC * DIMK / 4)
#define N_TOT4 (2 * N_WQ4 + 2 * N_WO4 + N_ENC4 + N_HID4)

__device__ __forceinline__ void cvt_resolve(int off, const float4** s, float4** d,
    const float* w_qkv, const float* w_add, const float* w_out,
    const float* w_add_out, const float* enc, const float* hid, int* rel)
{
    if (off < N_WQ4) { *s = (const float4*)w_qkv; *d = (float4*)g_Wq; *rel = off; }
    else if ((off -= N_WQ4) < N_WQ4) { *s = (const float4*)w_add; *d = (float4*)g_Wa; *rel = off; }
    else if ((off -= N_WQ4) < N_WO4) { *s = (const float4*)w_out; *d = (float4*)g_Wo; *rel = off; }
    else if ((off -= N_WO4) < N_WO4) { *s = (const float4*)w_add_out; *d = (float4*)g_Wao; *rel = off; }
    else if ((off -= N_WO4) < N_ENC4) { *s = (const float4*)enc; *d = (float4*)g_X; *rel = off; }
    else { *s = (const float4*)hid; *d = (float4*)(g_X + (size_t)S_TXTC * DIMK);
           *rel = off - N_ENC4; }
}

__global__ void cvt_all_kernel(const float* __restrict__ w_qkv,
                               const float* __restrict__ w_add,
                               const float* __restrict__ w_out,
                               const float* __restrict__ w_add_out,
                               const float* __restrict__ enc,
                               const float* __restrict__ hid)
{
    const int stride = gridDim.x * blockDim.x;
    int i = blockIdx.x * blockDim.x + threadIdx.x;
    for (; i + stride < N_TOT4; i += 2 * stride) {
        const float4 *s0, *s1; float4 *d0, *d1; int r0, r1;
        cvt_resolve(i, &s0, &d0, w_qkv, w_add, w_out, w_add_out, enc, hid, &r0);
        cvt_resolve(i + stride, &s1, &d1, w_qkv, w_add, w_out, w_add_out, enc, hid, &r1);
        float4 v0 = s0[r0];
        float4 v1 = s1[r1];
        v0.x = rtf(v0.x); v0.y = rtf(v0.y); v0.z = rtf(v0.z); v0.w = rtf(v0.w);
        v1.x = rtf(v1.x); v1.y = rtf(v1.y); v1.z = rtf(v1.z); v1.w = rtf(v1.w);
        d0[r0] = v0;
        d1[r1] = v1;
    }
    if (i < N_TOT4) {
        const float4* s; float4* d; int r;
        cvt_resolve(i, &s, &d, w_qkv, w_add, w_out, w_add_out, enc, hid, &r);
        float4 v = s[r];
        v.x = rtf(v.x); v.y = rtf(v.y); v.z = rtf(v.z); v.w = rtf(v.w);
        d[r] = v;
    }
}

// =================== GEMM: 128x256 tile, BK=32, cp.async 4-stage ============
#define AST_B 16384
#define BST_B 32768
#define GEMM_SMEM_BYTES (4 * AST_B + 4 * BST_B)   // 196608

__device__ __forceinline__ void gemm_issue_stage(
    const float* __restrict__ A, const float* __restrict__ W,
    uint32_t su, int slot, int kk, int t)
{
    const uint32_t sA = su + slot * AST_B;
    const uint32_t sB = su + 4 * AST_B + slot * BST_B;
#pragma unroll
    for (int l = 0; l < 4; l++) {
        int idx = t + l * 256;
        int row = idx >> 3, c = idx & 7;
        cp16(sA + row * 128 + ((c ^ (row & 7)) << 4),
             A + (size_t)row * DIMK + kk + c * 4);
    }
#pragma unroll
    for (int l = 0; l < 8; l++) {
        int idx = t + l * 256;
        int row = idx >> 3, c = idx & 7;
        cp16(sB + row * 128 + ((c ^ (row & 7)) << 4),
             W + (size_t)row * DIMK + kk + c * 4);
    }
    CP_COMMIT();
}

__device__ __forceinline__ void gemm_load_bf(uint32_t cB, int ks, int wn,
                                             int brow, int bsel,
                                             unsigned (&bf)[8][2])
{
#pragma unroll
    for (int p = 0; p < 4; p++) {
        int r = wn * 64 + p * 16 + brow;
        int c = ks * 2 + bsel;
        LDSM4(bf[2 * p][0], bf[2 * p][1], bf[2 * p + 1][0], bf[2 * p + 1][1],
              cB + r * 128 + ((c ^ (r & 7)) << 4));
    }
}

__device__ __forceinline__ void gemm_tf32_main(
    const float* __restrict__ A, const float* __restrict__ W,
    uint32_t su, float (&acc)[4][8][4], int t)
{
    const int lane = t & 31, wid = t >> 5;
    const int wm = wid >> 2, wn = wid & 3;
    const int arow = (lane & 7) + ((lane >> 3) & 1) * 8;
    const int asel = lane >> 4;
    const int brow = (lane & 7) + ((lane >> 4) & 1) * 8;
    const int bsel = (lane >> 3) & 1;

    gemm_issue_stage(A, W, su, 0, 0, t);
    gemm_issue_stage(A, W, su, 1, 32, t);
    gemm_issue_stage(A, W, su, 2, 64, t);

    const int NST = DIMK / 32;   // 96
    for (int i = 0; i < NST; i++) {
        if (i < NST - 2) CP_WAIT2();
        else if (i == NST - 2) CP_WAIT1();
        else CP_WAIT0();
        __syncthreads();
        if (i + 3 < NST)
            gemm_issue_stage(A, W, su, (i + 3) & 3, (i + 3) * 32, t);

        const int slot = i & 3;
        const uint32_t cA = su + slot * AST_B;
        const uint32_t cB = su + 4 * AST_B + slot * BST_B;

        unsigned bfb[2][8][2];
        gemm_load_bf(cB, 0, wn, brow, bsel, bfb[0]);
#pragma unroll
        for (int ks = 0; ks < 4; ks++) {
            unsigned af[4][4];
#pragma unroll
            for (int mt = 0; mt < 4; mt++) {
                int r = wm * 64 + mt * 16 + arow;
                int c = ks * 2 + asel;
                LDSM4(af[mt][0], af[mt][1], af[mt][2], af[mt][3],
                      cA + r * 128 + ((c ^ (r & 7)) << 4));
            }
            if (ks < 3)
                gemm_load_bf(cB, ks + 1, wn, brow, bsel, bfb[(ks + 1) & 1]);
#pragma unroll
            for (int mt = 0; mt < 4; mt++)
#pragma unroll
                for (int nt = 0; nt < 8; nt++)
                    mma8(acc[mt][nt], af[mt], bfb[ks & 1][nt]);
        }
    }
}

// ------- kernel 1: QKV projection + fused RMSNorm/RoPE/V-transpose ----------
__global__ __launch_bounds__(256, 1) void gemm_qkv_kernel(
    const float* __restrict__ b_img, const float* __restrict__ b_txt,
    const float* __restrict__ cosT, const float* __restrict__ sinT,
    const float* __restrict__ nq,  const float* __restrict__ nk,
    const float* __restrict__ naq, const float* __restrict__ nak)
{
    extern __shared__ unsigned gsm[];
    const uint32_t su = smem_u32(gsm);
    const int m0 = blockIdx.x * 128;
    const int n0 = blockIdx.y * 256;
    const bool txt = (m0 < S_TXTC);
    const float* A    = g_X + (size_t)m0 * DIMK;
    const float* W    = (txt ? g_Wa : g_Wq) + (size_t)n0 * DIMK;
    const float* bias = txt ? b_txt : b_img;

    const int t = threadIdx.x;
    float acc[4][8][4];
#pragma unroll
    for (int i = 0; i < 4; i++)
#pragma unroll
        for (int j = 0; j < 8; j++)
#pragma unroll
            for (int c = 0; c < 4; c++) acc[i][j][c] = 0.f;

    gemm_tf32_main(A, W, su, acc, t);

    const int lane = t & 31, wid = t >> 5;
    const int g = lane >> 2, t4 = lane & 3;
    const int wm = wid >> 2, wn = wid & 3;

#pragma unroll
    for (int mt = 0; mt < 4; mt++)
#pragma unroll
        for (int nt = 0; nt < 8; nt++) {
            int c = n0 + wn * 64 + nt * 8 + t4 * 2;
            acc[mt][nt][0] += bias[c];     acc[mt][nt][1] += bias[c + 1];
            acc[mt][nt][2] += bias[c];     acc[mt][nt][3] += bias[c + 1];
        }

    const int sec = n0 / DIMK;            // 0=Q 1=K 2=V
    const int ncol0 = n0 - sec * DIMK;
    __syncthreads();

    if (sec < 2) {
        float* sums = (float*)gsm;
#pragma unroll
        for (int mt = 0; mt < 4; mt++) {
            float p0 = 0.f, p1 = 0.f;
#pragma unroll
            for (int nt = 0; nt < 8; nt++) {
                p0 += acc[mt][nt][0] * acc[mt][nt][0]
                    + acc[mt][nt][1] * acc[mt][nt][1];
                p1 += acc[mt][nt][2] * acc[mt][nt][2]
                    + acc[mt][nt][3] * acc[mt][nt][3];
            }
            p0 += __shfl_xor_sync(0xffffffffu, p0, 1);
            p0 += __shfl_xor_sync(0xffffffffu, p0, 2);
            p1 += __shfl_xor_sync(0xffffffffu, p1, 1);
            p1 += __shfl_xor_sync(0xffffffffu, p1, 2);
            if (t4 == 0) {
                int r = wm * 64 + mt * 16 + g;
                sums[wn * 128 + r] = p0;
                sums[wn * 128 + r + 8] = p1;
            }
        }
        __syncthreads();

        const float* wsel = (sec == 0) ? (txt ? naq : nq) : (txt ? nak : nk);
        float* dstb = (sec == 0) ? g_Q : g_K;
        const float oscale = (sec == 0) ? (QSCALE * LOG2E) : 1.0f;
        const int h = ncol0 / 128 + (wn >> 1);
        const int dbase = (wn & 1) * 64;

#pragma unroll
        for (int mt = 0; mt < 4; mt++) {
            int r0 = wm * 64 + mt * 16 + g;
            float tot0 = sums[wn * 128 + r0] + sums[(wn ^ 1) * 128 + r0];
            float tot1 = sums[wn * 128 + r0 + 8] + sums[(wn ^ 1) * 128 + r0 + 8];
            float rs0 = rsqrtf(tot0 * (1.0f / HDIM) + EPSV);
            float rs1 = rsqrtf(tot1 * (1.0f / HDIM) + EPSV);
            int s0 = m0 + r0, s1 = s0 + 8;
            float* d0 = dstb + ((size_t)h * S_TOT + s0) * HDIM + dbase;
            float* d1 = dstb + ((size_t)h * S_TOT + s1) * HDIM + dbase;
#pragma unroll
            for (int nt = 0; nt < 8; nt++) {
                int d = dbase + nt * 8 + t4 * 2;
                float w0 = wsel[d], w1 = wsel[d + 1];
                int i = d >> 1;
                float c0 = cosT[s0 * 64 + i], n0r = sinT[s0 * 64 + i];
                float c1 = cosT[s1 * 64 + i], n1r = sinT[s1 * 64 + i];
                float a0 = acc[mt][nt][0] * rs0 * w0;
                float a1 = acc[mt][nt][1] * rs0 * w1;
                float b0 = acc[mt][nt][2] * rs1 * w0;
                float b1 = acc[mt][nt][3] * rs1 * w1;
                float2 v0 = make_float2(rtf((a0 * c0 - a1 * n0r) * oscale),
                                        rtf((a1 * c0 + a0 * n0r) * oscale));
                float2 v1 = make_float2(rtf((b0 * c1 - b1 * n1r) * oscale),
                                        rtf((b1 * c1 + b0 * n1r) * oscale));
                *(float2*)(d0 + nt * 8 + t4 * 2) = v0;
                *(float2*)(d1 + nt * 8 + t4 * 2) = v1;
            }
        }
    } else {
        float* vsm = (float*)gsm;
#pragma unroll
        for (int mt = 0; mt < 4; mt++) {
            int r0 = wm * 64 + mt * 16 + g;
#pragma unroll
            for (int nt = 0; nt < 8; nt++) {
                int col = wn * 64 + nt * 8 + t4 * 2;
                vsm[col * 132 + r0]           = rtf(acc[mt][nt][0]);
                vsm[(col + 1) * 132 + r0]     = rtf(acc[mt][nt][1]);
                vsm[col * 132 + r0 + 8]       = rtf(acc[mt][nt][2]);
                vsm[(col + 1) * 132 + r0 + 8] = rtf(acc[mt][nt][3]);
            }
        }
        __syncthreads();
        const int h0 = ncol0 / 128;
#pragma unroll
        for (int pass = 0; pass < 8; pass++) {
            int dcol = pass * 32 + (t >> 3);
            int sb = (t & 7) * 16;
            int h = h0 + (dcol >> 7);
            int dd = dcol & 127;
            float* dst = g_Vt + ((size_t)h * HDIM + dd) * S_TOT + m0 + sb;
            const float* srcr = vsm + dcol * 132 + sb;
#pragma unroll
            for (int j = 0; j < 16; j += 4)
                *(float4*)(dst + j) = make_float4(srcr[j], srcr[j + 1],
                                                  srcr[j + 2], srcr[j + 3]);
        }
    }
}

// ---------------- kernel 4: output projections + scatter --------------------
__global__ __launch_bounds__(256, 1) void gemm_out_kernel(
    const float* __restrict__ b_img, const float* __restrict__ b_txt,
    float* __restrict__ out)
{
    extern __shared__ unsigned gsm[];
    const uint32_t su = smem_u32(gsm);
    const int m0 = blockIdx.x * 128;
    const int n0 = blockIdx.y * 256;
    const bool txt = (m0 < S_TXTC);
    const float* A    = g_O + (size_t)m0 * DIMK;
    const float* W    = (txt ? g_Wao : g_Wo) + (size_t)n0 * DIMK;
    const float* bias = txt ? b_txt : b_img;

    const int t = threadIdx.x;
    float acc[4][8][4];
#pragma unroll
    for (int i = 0; i < 4; i++)
#pragma unroll
        for (int j = 0; j < 8; j++)
#pragma unroll
            for (int c = 0; c < 4; c++) acc[i][j][c] = 0.f;

    gemm_tf32_main(A, W, su, acc, t);

    const int lane = t & 31, wid = t >> 5;
    const int g = lane >> 2, t4 = lane & 3;
    const int wm = wid >> 2, wn = wid & 3;
#pragma unroll
    for (int mt = 0; mt < 4; mt++) {
        int s = m0 + wm * 64 + mt * 16 + g;
        int orow0 = txt ? (S_IMGC + s) : (s - S_TXTC);
        int orow1 = orow0 + 8;
#pragma unroll
        for (int nt = 0; nt < 8; nt++) {
            int c = n0 + wn * 64 + nt * 8 + t4 * 2;
            float2 v0 = make_float2(acc[mt][nt][0] + bias[c],
                                    acc[mt][nt][1] + bias[c + 1]);
            float2 v1 = make_float2(acc[mt][nt][2] + bias[c],
                                    acc[mt][nt][3] + bias[c + 1]);
            *(float2*)(out + (size_t)orow0 * DIMK + c) = v0;
            *(float2*)(out + (size_t)orow1 * DIMK + c) = v1;
        }
    }
}

// ====== flash v6 (restored): 128q-tile, two-tile S/softmax pipeline =========
#define KS_B   33792
#define VT_B   34816
#define VT_OFF (2 * KS_B)              // 67584
#define PS_OFF (VT_OFF + 2 * VT_B)     // 137216
#define FLASH_SMEM_BYTES (PS_OFF + VT_B)   // 172032

__device__ __forceinline__ void flash_issue_k(const float* __restrict__ Kg,
                                              uint32_t ksb, int t)
{
#pragma unroll
    for (int l = 0; l < 8; l++) {
        int idx = t + l * 256;
        int r = idx >> 5, c = idx & 31;
        cp16(ksb + (uint32_t)(r * 528 + c * 16), Kg + (size_t)r * HDIM + c * 4);
    }
}
__device__ __forceinline__ void flash_issue_v(const float* __restrict__ Vt,
                                              uint32_t vtb, int t)
{
#pragma unroll
    for (int l = 0; l < 8; l++) {
        int idx = t + l * 256;
        int r = idx >> 4, c = idx & 15;
        cp16(vtb + (uint32_t)(r * 272 + c * 16), Vt + (size_t)r * S_TOT + c * 4);
    }
}

__device__ __forceinline__ void flash_S(uint32_t ksb, const unsigned (&qf)[16][4],
                                        const uint32_t (&okk)[4], float (&sc)[8][4])
{
#pragma unroll
    for (int nt = 0; nt < 8; nt++)
#pragma unroll
        for (int c = 0; c < 4; c++) sc[nt][c] = 0.f;
#pragma unroll
    for (int ks = 0; ks < 16; ks++) {
        unsigned bf[8][2];
#pragma unroll
        for (int p = 0; p < 4; p++)
            LDSM4(bf[2 * p][0], bf[2 * p][1], bf[2 * p + 1][0],
                  bf[2 * p + 1][1], ksb + okk[p] + ks * 32);
#pragma unroll
        for (int nt = 0; nt < 8; nt++)
            mma8(sc[nt], qf[ks], bf[nt]);
    }
}

__global__ __launch_bounds__(256, 1) void flash_v6_kernel()
{
    extern __shared__ unsigned fsm[];
    const uint32_t su = smem_u32(fsm);

    const int qt = blockIdx.x, h = blockIdx.y;
    const int t = threadIdx.x, lane = t & 31, wid = t >> 5;
    const float* Kg0 = g_K + (size_t)h * S_TOT * HDIM;
    const float* Vt0 = g_Vt + (size_t)h * HDIM * S_TOT;

    const int g = lane >> 2, t4 = lane & 3;
    const int qb = wid * 16;

    const int brow = (lane & 7) + ((lane >> 4) & 1) * 8;
    const int bcol = ((lane >> 3) & 1) * 4;
    const int parow = (lane & 7) + ((lane >> 3) & 1) * 8;
    const int pacol = (lane >> 4) * 4;
    uint32_t okk[4], ovv[8], opa;
#pragma unroll
    for (int p = 0; p < 4; p++) okk[p] = (uint32_t)((p * 16 + brow) * 132 + bcol) * 4;
#pragma unroll
    for (int p = 0; p < 8; p++) ovv[p] = (uint32_t)((p * 16 + brow) * 68 + bcol) * 4;
    opa = (uint32_t)((qb + parow) * 68 + pacol) * 4;

    flash_issue_k(Kg0, su, t);
    flash_issue_v(Vt0, su + VT_OFF, t);
    CP_COMMIT();

    unsigned qf[16][4];
    const float* Qg = g_Q + ((size_t)h * S_TOT + qt * 128) * HDIM;
#pragma unroll
    for (int ks = 0; ks < 16; ks++) {
        int k = ks * 8;
        qf[ks][0] = __float_as_uint(Qg[(size_t)(qb + g) * HDIM + k + t4]);
        qf[ks][1] = __float_as_uint(Qg[(size_t)(qb + g + 8) * HDIM + k + t4]);
        qf[ks][2] = __float_as_uint(Qg[(size_t)(qb + g) * HDIM + k + t4 + 4]);
        qf[ks][3] = __float_as_uint(Qg[(size_t)(qb + g + 8) * HDIM + k + t4 + 4]);
    }

    float o[16][4];
#pragma unroll
    for (int dt = 0; dt < 16; dt++)
#pragma unroll
        for (int c = 0; c < 4; c++) o[dt][c] = 0.f;
    float mrow[2] = {-1e30f, -1e30f}, lrow[2] = {0.f, 0.f};

    CP_WAIT0();
    __syncthreads();
    flash_issue_k(Kg0 + (size_t)64 * HDIM, su + KS_B, t);
    CP_COMMIT();

    float sc[8][4];
    flash_S(su, qf, okk, sc);

    const int NT = S_TOT / 64;   // 40
    for (int kt = 0; kt < NT; kt++) {
        const int b = kt & 1;
        if (kt + 1 < NT) {
            flash_issue_v(Vt0 + (size_t)(kt + 1) * 64,
                          su + VT_OFF + (b ^ 1) * VT_B, t);
            CP_COMMIT();
            CP_WAIT1();
        } else {
            CP_WAIT0();
        }
        __syncthreads();
        if (kt + 2 < NT) {
            flash_issue_k(Kg0 + (size_t)(kt + 2) * 64 * HDIM, su + b * KS_B, t);
            CP_COMMIT();
        }
        float scn[8][4];
        if (kt + 1 < NT)
            flash_S(su + ((kt + 1) & 1) * KS_B, qf, okk, scn);

        float mx0 = -1e30f, mx1 = -1e30f;
#pragma unroll
        for (int nt = 0; nt < 8; nt++) {
            mx0 = fmaxf(mx0, fmaxf(sc[nt][0], sc[nt][1]));
            mx1 = fmaxf(mx1, fmaxf(sc[nt][2], sc[nt][3]));
        }
        mx0 = fmaxf(mx0, __shfl_xor_sync(0xffffffffu, mx0, 1));
        mx0 = fmaxf(mx0, __shfl_xor_sync(0xffffffffu, mx0, 2));
        mx1 = fmaxf(mx1, __shfl_xor_sync(0xffffffffu, mx1, 1));
        mx1 = fmaxf(mx1, __shfl_xor_sync(0xffffffffu, mx1, 2));
        float m0n = fmaxf(mrow[0], mx0), m1n = fmaxf(mrow[1], mx1);
        float a0 = ex2(mrow[0] - m0n), a1 = ex2(mrow[1] - m1n);
        mrow[0] = m0n; mrow[1] = m1n;

        float rs0 = 0.f, rs1 = 0.f;
#pragma unroll
        for (int nt = 0; nt < 8; nt++) {
            sc[nt][0] = ex2(sc[nt][0] - m0n);
            sc[nt][1] = ex2(sc[nt][1] - m0n);
            sc[nt][2] = ex2(sc[nt][2] - m1n);
            sc[nt][3] = ex2(sc[nt][3] - m1n);
            rs0 += sc[nt][0] + sc[nt][1];
            rs1 += sc[nt][2] + sc[nt][3];
        }
        rs0 += __shfl_xor_sync(0xffffffffu, rs0, 1);
        rs0 += __shfl_xor_sync(0xffffffffu, rs0, 2);
        rs1 += __shfl_xor_sync(0xffffffffu, rs1, 1);
        rs1 += __shfl_xor_sync(0xffffffffu, rs1, 2);
        lrow[0] = lrow[0] * a0 + rs0;
        lrow[1] = lrow[1] * a1 + rs1;

#pragma unroll
        for (int dt = 0; dt < 16; dt++) {
            o[dt][0] *= a0; o[dt][1] *= a0;
            o[dt][2] *= a1; o[dt][3] *= a1;
        }

        const uint32_t psb = su + PS_OFF;
#pragma unroll
        for (int nt = 0; nt < 8; nt++) {
            uint32_t pb = psb + (uint32_t)((qb + g) * 68 + nt * 8 + t4 * 2) * 4;
            STS32(pb,     f2tf(sc[nt][0]));
            STS32(pb + 4, f2tf(sc[nt][1]));
            STS32(pb + 8 * 68 * 4,     f2tf(sc[nt][2]));
            STS32(pb + 8 * 68 * 4 + 4, f2tf(sc[nt][3]));
        }
        __syncwarp();

        const uint32_t vtb = su + VT_OFF + b * VT_B;
#pragma unroll
        for (int ks = 0; ks < 8; ks++) {
            unsigned pa[4];
            LDSM4(pa[0], pa[1], pa[2], pa[3], psb + opa + ks * 32);
#pragma unroll
            for (int p = 0; p < 8; p++) {
                unsigned vf0[2], vf1[2];
                LDSM4(vf0[0], vf0[1], vf1[0], vf1[1], vtb + ovv[p] + ks * 32);
                mma8(o[2 * p], pa, vf0);
                mma8(o[2 * p + 1], pa, vf1);
            }
        }

        if (kt + 1 < NT) {
#pragma unroll
            for (int nt = 0; nt < 8; nt++)
#pragma unroll
                for (int c = 0; c < 4; c++) sc[nt][c] = scn[nt][c];
        }
        __syncthreads();
    }

    float inv0 = 1.0f / lrow[0], inv1 = 1.0f / lrow[1];
    int s0 = qt * 128 + qb + g;
    float* dst0 = g_O + (size_t)s0 * DIMK + h * HDIM;
    float* dst1 = dst0 + (size_t)8 * DIMK;
#pragma unroll
    for (int dt = 0; dt < 16; dt++) {
        int d = dt * 8 + t4 * 2;
        float2 w0 = make_float2(rtf(o[dt][0] * inv0), rtf(o[dt][1] * inv0));
        float2 w1 = make_float2(rtf(o[dt][2] * inv1), rtf(o[dt][3] * inv1));
        *(float2*)(dst0 + d) = w0;
        *(float2*)(dst1 + d) = w1;
    }
}

// ---------------- launch ----------------------------------------------------
extern "C" void kernel_launch(void* const* d_in, const int* in_sizes, int n_in,
                              void* d_out, int out_size)
{
    const float* hid       = (const float*)d_in[0];
    const float* enc       = (const float*)d_in[1];
    const float* cosT      = (const float*)d_in[2];
    const float* sinT      = (const float*)d_in[3];
    const float* w_qkv     = (const float*)d_in[4];
    const float* b_qkv     = (const float*)d_in[5];
    const float* w_add     = (const float*)d_in[6];
    const float* b_add     = (const float*)d_in[7];
    const float* nq        = (const float*)d_in[8];
    const float* nk        = (const float*)d_in[9];
    const float* naq       = (const float*)d_in[10];
    const float* nak       = (const float*)d_in[11];
    const float* w_out     = (const float*)d_in[12];
    const float* b_out     = (const float*)d_in[13];
    const float* w_add_out = (const float*)d_in[14];
    const float* b_add_out = (const float*)d_in[15];
    float* out = (float*)d_out;

    static bool attr_done = false;
    if (!attr_done) {
        cudaFuncSetAttribute(gemm_qkv_kernel,
            cudaFuncAttributeMaxDynamicSharedMemorySize, GEMM_SMEM_BYTES);
        cudaFuncSetAttribute(gemm_out_kernel,
            cudaFuncAttributeMaxDynamicSharedMemorySize, GEMM_SMEM_BYTES);
        cudaFuncSetAttribute(flash_v6_kernel,
            cudaFuncAttributeMaxDynamicSharedMemorySize, FLASH_SMEM_BYTES);
        attr_done = true;
    }

    cvt_all_kernel<<<2048, 256>>>(w_qkv, w_add, w_out, w_add_out, enc, hid);

    gemm_qkv_kernel<<<dim3(S_TOT / 128, E3 / 256), 256, GEMM_SMEM_BYTES>>>(
        b_qkv, b_add, cosT, sinT, nq, nk, naq, nak);

    flash_v6_kernel<<<dim3(S_TOT / 128, NHEADS), 256, FLASH_SMEM_BYTES>>>();

    gemm_out_kernel<<<dim3(S_TOT / 128, DIMK / 256), 256, GEMM_SMEM_BYTES>>>(
        b_out, b_add_out, out);
}

// round 17
// speedup vs baseline: 1.0656x; 1.0331x over previous
#include <cuda_runtime.h>
#include <cstdint>

#define S_TOT  2560
#define S_TXTC 512
#define S_IMGC 2048
#define DIMK   3072
#define NHEADS 24
#define HDIM   128
#define E3     9216
#define EPSV   1e-6f
#define QSCALE 0.088388347648318447f   // 1/sqrt(128)
#define LOG2E  1.4426950408889634f

// ---------------- scratch ---------------------------------------------------
static __device__ float g_Q[NHEADS * S_TOT * HDIM];         // rounded, *log2e
static __device__ float g_K[NHEADS * S_TOT * HDIM];
static __device__ float g_Vt[NHEADS * HDIM * S_TOT];        // [h][d][s]
static __device__ float g_O[S_TOT * DIMK];
static __device__ float g_Wq[E3 * DIMK];
static __device__ float g_Wa[E3 * DIMK];
static __device__ float g_Wo[DIMK * DIMK];
static __device__ float g_Wao[DIMK * DIMK];
static __device__ float g_X[S_TOT * DIMK];
static __device__ float g_Fo[2][S_TOT * DIMK];              // unnormalized attn
static __device__ float g_Fm[2][NHEADS * S_TOT];            // row max (log2)
static __device__ float g_Fl[2][NHEADS * S_TOT];            // row sum
static __device__ float g_Pout[3][S_TOT * DIMK];            // split-K partials

// ---------------- helpers ---------------------------------------------------
__device__ __forceinline__ unsigned f2tf(float x) {
    unsigned u;
    asm("cvt.rna.tf32.f32 %0, %1;" : "=r"(u) : "f"(x));
    return u;
}
__device__ __forceinline__ float rtf(float x) { return __uint_as_float(f2tf(x)); }
__device__ __forceinline__ float ex2(float x) {
    float r;
    asm("ex2.approx.f32 %0, %1;" : "=f"(r) : "f"(x));
    return r;
}
__device__ __forceinline__ uint32_t smem_u32(const void* p) {
    uint32_t a;
    asm("{ .reg .u64 t; cvta.to.shared.u64 t, %1; cvt.u32.u64 %0, t; }"
        : "=r"(a) : "l"(p));
    return a;
}
__device__ __forceinline__ void mma8(float (&d)[4], const unsigned (&a)[4],
                                     const unsigned (&b)[2]) {
    asm volatile(
        "mma.sync.aligned.m16n8k8.row.col.f32.tf32.tf32.f32 "
        "{%0,%1,%2,%3}, {%4,%5,%6,%7}, {%8,%9}, {%0,%1,%2,%3};\n"
        : "+f"(d[0]), "+f"(d[1]), "+f"(d[2]), "+f"(d[3])
        : "r"(a[0]), "r"(a[1]), "r"(a[2]), "r"(a[3]), "r"(b[0]), "r"(b[1]));
}
#define LDSM4(r0, r1, r2, r3, addr)                                            \
    asm volatile("ldmatrix.sync.aligned.m8n8.x4.shared.b16 {%0,%1,%2,%3}, [%4];" \
                 : "=r"(r0), "=r"(r1), "=r"(r2), "=r"(r3) : "r"(addr))
#define STS32(addr, x)                                                         \
    asm volatile("st.shared.b32 [%0], %1;" :: "r"(addr), "r"(x) : "memory")
__device__ __forceinline__ void cp16(uint32_t s, const void* g) {
    asm volatile("cp.async.cg.shared.global [%0], [%1], 16;" :: "r"(s), "l"(g));
}
#define CP_COMMIT() asm volatile("cp.async.commit_group;" ::: "memory")
#define CP_WAIT2()  asm volatile("cp.async.wait_group 2;" ::: "memory")
#define CP_WAIT1()  asm volatile("cp.async.wait_group 1;" ::: "memory")
#define CP_WAIT0()  asm volatile("cp.async.wait_group 0;" ::: "memory")

// ---------------- kernel 0: fused tf32 pre-round (x2 ILP) -------------------
#define N_WQ4  (E3 * DIMK / 4)
#define N_WO4  (DIMK * DIMK / 4)
#define N_ENC4 (S_TXTC * DIMK / 4)
#define N_HID4 (S_IMGC * DIMK / 4)
#define N_TOT4 (2 * N_WQ4 + 2 * N_WO4 + N_ENC4 + N_HID4)

__device__ __forceinline__ void cvt_resolve(int off, const float4** s, float4** d,
    const float* w_qkv, const float* w_add, const float* w_out,
    const float* w_add_out, const float* enc, const float* hid, int* rel)
{
    if (off < N_WQ4) { *s = (const float4*)w_qkv; *d = (float4*)g_Wq; *rel = off; }
    else if ((off -= N_WQ4) < N_WQ4) { *s = (const float4*)w_add; *d = (float4*)g_Wa; *rel = off; }
    else if ((off -= N_WQ4) < N_WO4) { *s = (const float4*)w_out; *d = (float4*)g_Wo; *rel = off; }
    else if ((off -= N_WO4) < N_WO4) { *s = (const float4*)w_add_out; *d = (float4*)g_Wao; *rel = off; }
    else if ((off -= N_WO4) < N_ENC4) { *s = (const float4*)enc; *d = (float4*)g_X; *rel = off; }
    else { *s = (const float4*)hid; *d = (float4*)(g_X + (size_t)S_TXTC * DIMK);
           *rel = off - N_ENC4; }
}

__global__ void cvt_all_kernel(const float* __restrict__ w_qkv,
                               const float* __restrict__ w_add,
                               const float* __restrict__ w_out,
                               const float* __restrict__ w_add_out,
                               const float* __restrict__ enc,
                               const float* __restrict__ hid)
{
    const int stride = gridDim.x * blockDim.x;
    int i = blockIdx.x * blockDim.x + threadIdx.x;
    for (; i + stride < N_TOT4; i += 2 * stride) {
        const float4 *s0, *s1; float4 *d0, *d1; int r0, r1;
        cvt_resolve(i, &s0, &d0, w_qkv, w_add, w_out, w_add_out, enc, hid, &r0);
        cvt_resolve(i + stride, &s1, &d1, w_qkv, w_add, w_out, w_add_out, enc, hid, &r1);
        float4 v0 = s0[r0];
        float4 v1 = s1[r1];
        v0.x = rtf(v0.x); v0.y = rtf(v0.y); v0.z = rtf(v0.z); v0.w = rtf(v0.w);
        v1.x = rtf(v1.x); v1.y = rtf(v1.y); v1.z = rtf(v1.z); v1.w = rtf(v1.w);
        d0[r0] = v0;
        d1[r1] = v1;
    }
    if (i < N_TOT4) {
        const float4* s; float4* d; int r;
        cvt_resolve(i, &s, &d, w_qkv, w_add, w_out, w_add_out, enc, hid, &r);
        float4 v = s[r];
        v.x = rtf(v.x); v.y = rtf(v.y); v.z = rtf(v.z); v.w = rtf(v.w);
        d[r] = v;
    }
}

// =================== GEMM: 128x256 tile, BK=32, cp.async 4-stage ============
#define AST_B 16384
#define BST_B 32768
#define GEMM_SMEM_BYTES (4 * AST_B + 4 * BST_B)   // 196608

__device__ __forceinline__ void gemm_issue_stage(
    const float* __restrict__ A, const float* __restrict__ W,
    uint32_t su, int slot, int kk, int t)
{
    const uint32_t sA = su + slot * AST_B;
    const uint32_t sB = su + 4 * AST_B + slot * BST_B;
#pragma unroll
    for (int l = 0; l < 4; l++) {
        int idx = t + l * 256;
        int row = idx >> 3, c = idx & 7;
        cp16(sA + row * 128 + ((c ^ (row & 7)) << 4),
             A + (size_t)row * DIMK + kk + c * 4);
    }
#pragma unroll
    for (int l = 0; l < 8; l++) {
        int idx = t + l * 256;
        int row = idx >> 3, c = idx & 7;
        cp16(sB + row * 128 + ((c ^ (row & 7)) << 4),
             W + (size_t)row * DIMK + kk + c * 4);
    }
    CP_COMMIT();
}

__device__ __forceinline__ void gemm_tf32_main(
    const float* __restrict__ A, const float* __restrict__ W,
    uint32_t su, float (&acc)[4][8][4], int t, int NST)
{
    const int lane = t & 31, wid = t >> 5;
    const int wm = wid >> 2, wn = wid & 3;
    const int arow = (lane & 7) + ((lane >> 3) & 1) * 8;
    const int asel = lane >> 4;
    const int brow = (lane & 7) + ((lane >> 4) & 1) * 8;
    const int bsel = (lane >> 3) & 1;

    gemm_issue_stage(A, W, su, 0, 0, t);
    gemm_issue_stage(A, W, su, 1, 32, t);
    gemm_issue_stage(A, W, su, 2, 64, t);

    for (int i = 0; i < NST; i++) {
        if (i < NST - 2) CP_WAIT2();
        else if (i == NST - 2) CP_WAIT1();
        else CP_WAIT0();
        __syncthreads();
        if (i + 3 < NST)
            gemm_issue_stage(A, W, su, (i + 3) & 3, (i + 3) * 32, t);

        const int slot = i & 3;
        const uint32_t cA = su + slot * AST_B;
        const uint32_t cB = su + 4 * AST_B + slot * BST_B;
#pragma unroll
        for (int ks = 0; ks < 4; ks++) {
            unsigned af[4][4], bf[8][2];
#pragma unroll
            for (int mt = 0; mt < 4; mt++) {
                int r = wm * 64 + mt * 16 + arow;
                int c = ks * 2 + asel;
                LDSM4(af[mt][0], af[mt][1], af[mt][2], af[mt][3],
                      cA + r * 128 + ((c ^ (r & 7)) << 4));
            }
#pragma unroll
            for (int p = 0; p < 4; p++) {
                int r = wn * 64 + p * 16 + brow;
                int c = ks * 2 + bsel;
                LDSM4(bf[2 * p][0], bf[2 * p][1], bf[2 * p + 1][0],
                      bf[2 * p + 1][1], cB + r * 128 + ((c ^ (r & 7)) << 4));
            }
#pragma unroll
            for (int mt = 0; mt < 4; mt++)
#pragma unroll
                for (int nt = 0; nt < 8; nt++)
                    mma8(acc[mt][nt], af[mt], bf[nt]);
        }
    }
}

// ------- kernel 1: QKV projection + fused RMSNorm/RoPE/V-transpose ----------
__global__ __launch_bounds__(256, 1) void gemm_qkv_kernel(
    const float* __restrict__ b_img, const float* __restrict__ b_txt,
    const float* __restrict__ cosT, const float* __restrict__ sinT,
    const float* __restrict__ nq,  const float* __restrict__ nk,
    const float* __restrict__ naq, const float* __restrict__ nak)
{
    extern __shared__ unsigned gsm[];
    const uint32_t su = smem_u32(gsm);
    const int m0 = blockIdx.x * 128;
    const int n0 = blockIdx.y * 256;
    const bool txt = (m0 < S_TXTC);
    const float* A    = g_X + (size_t)m0 * DIMK;
    const float* W    = (txt ? g_Wa : g_Wq) + (size_t)n0 * DIMK;
    const float* bias = txt ? b_txt : b_img;

    const int t = threadIdx.x;
    float acc[4][8][4];
#pragma unroll
    for (int i = 0; i < 4; i++)
#pragma unroll
        for (int j = 0; j < 8; j++)
#pragma unroll
            for (int c = 0; c < 4; c++) acc[i][j][c] = 0.f;

    gemm_tf32_main(A, W, su, acc, t, 96);

    const int lane = t & 31, wid = t >> 5;
    const int g = lane >> 2, t4 = lane & 3;
    const int wm = wid >> 2, wn = wid & 3;

#pragma unroll
    for (int mt = 0; mt < 4; mt++)
#pragma unroll
        for (int nt = 0; nt < 8; nt++) {
            int c = n0 + wn * 64 + nt * 8 + t4 * 2;
            acc[mt][nt][0] += bias[c];     acc[mt][nt][1] += bias[c + 1];
            acc[mt][nt][2] += bias[c];     acc[mt][nt][3] += bias[c + 1];
        }

    const int sec = n0 / DIMK;            // 0=Q 1=K 2=V
    const int ncol0 = n0 - sec * DIMK;
    __syncthreads();

    if (sec < 2) {
        float* sums = (float*)gsm;
#pragma unroll
        for (int mt = 0; mt < 4; mt++) {
            float p0 = 0.f, p1 = 0.f;
#pragma unroll
            for (int nt = 0; nt < 8; nt++) {
                p0 += acc[mt][nt][0] * acc[mt][nt][0]
                    + acc[mt][nt][1] * acc[mt][nt][1];
                p1 += acc[mt][nt][2] * acc[mt][nt][2]
                    + acc[mt][nt][3] * acc[mt][nt][3];
            }
            p0 += __shfl_xor_sync(0xffffffffu, p0, 1);
            p0 += __shfl_xor_sync(0xffffffffu, p0, 2);
            p1 += __shfl_xor_sync(0xffffffffu, p1, 1);
            p1 += __shfl_xor_sync(0xffffffffu, p1, 2);
            if (t4 == 0) {
                int r = wm * 64 + mt * 16 + g;
                sums[wn * 128 + r] = p0;
                sums[wn * 128 + r + 8] = p1;
            }
        }
        __syncthreads();

        const float* wsel = (sec == 0) ? (txt ? naq : nq) : (txt ? nak : nk);
        float* dstb = (sec == 0) ? g_Q : g_K;
        const float oscale = (sec == 0) ? (QSCALE * LOG2E) : 1.0f;
        const int h = ncol0 / 128 + (wn >> 1);
        const int dbase = (wn & 1) * 64;

#pragma unroll
        for (int mt = 0; mt < 4; mt++) {
            int r0 = wm * 64 + mt * 16 + g;
            float tot0 = sums[wn * 128 + r0] + sums[(wn ^ 1) * 128 + r0];
            float tot1 = sums[wn * 128 + r0 + 8] + sums[(wn ^ 1) * 128 + r0 + 8];
            float rs0 = rsqrtf(tot0 * (1.0f / HDIM) + EPSV);
            float rs1 = rsqrtf(tot1 * (1.0f / HDIM) + EPSV);
            int s0 = m0 + r0, s1 = s0 + 8;
            float* d0 = dstb + ((size_t)h * S_TOT + s0) * HDIM + dbase;
            float* d1 = dstb + ((size_t)h * S_TOT + s1) * HDIM + dbase;
#pragma unroll
            for (int nt = 0; nt < 8; nt++) {
                int d = dbase + nt * 8 + t4 * 2;
                float w0 = wsel[d], w1 = wsel[d + 1];
                int i = d >> 1;
                float c0 = cosT[s0 * 64 + i], n0r = sinT[s0 * 64 + i];
                float c1 = cosT[s1 * 64 + i], n1r = sinT[s1 * 64 + i];
                float a0 = acc[mt][nt][0] * rs0 * w0;
                float a1 = acc[mt][nt][1] * rs0 * w1;
                float b0 = acc[mt][nt][2] * rs1 * w0;
                float b1 = acc[mt][nt][3] * rs1 * w1;
                float2 v0 = make_float2(rtf((a0 * c0 - a1 * n0r) * oscale),
                                        rtf((a1 * c0 + a0 * n0r) * oscale));
                float2 v1 = make_float2(rtf((b0 * c1 - b1 * n1r) * oscale),
                                        rtf((b1 * c1 + b0 * n1r) * oscale));
                *(float2*)(d0 + nt * 8 + t4 * 2) = v0;
                *(float2*)(d1 + nt * 8 + t4 * 2) = v1;
            }
        }
    } else {
        float* vsm = (float*)gsm;
#pragma unroll
        for (int mt = 0; mt < 4; mt++) {
            int r0 = wm * 64 + mt * 16 + g;
#pragma unroll
            for (int nt = 0; nt < 8; nt++) {
                int col = wn * 64 + nt * 8 + t4 * 2;
                vsm[col * 132 + r0]           = rtf(acc[mt][nt][0]);
                vsm[(col + 1) * 132 + r0]     = rtf(acc[mt][nt][1]);
                vsm[col * 132 + r0 + 8]       = rtf(acc[mt][nt][2]);
                vsm[(col + 1) * 132 + r0 + 8] = rtf(acc[mt][nt][3]);
            }
        }
        __syncthreads();
        const int h0 = ncol0 / 128;
#pragma unroll
        for (int pass = 0; pass < 8; pass++) {
            int dcol = pass * 32 + (t >> 3);
            int sb = (t & 7) * 16;
            int h = h0 + (dcol >> 7);
            int dd = dcol & 127;
            float* dst = g_Vt + ((size_t)h * HDIM + dd) * S_TOT + m0 + sb;
            const float* srcr = vsm + dcol * 132 + sb;
#pragma unroll
            for (int j = 0; j < 16; j += 4)
                *(float4*)(dst + j) = make_float4(srcr[j], srcr[j + 1],
                                                  srcr[j + 2], srcr[j + 3]);
        }
    }
}

// ---------------- kernel 4a: output projection split-K partials -------------
__global__ __launch_bounds__(256, 1) void gemm_out_kernel(
    float* __restrict__ unused)
{
    extern __shared__ unsigned gsm[];
    const uint32_t su = smem_u32(gsm);
    const int m0 = blockIdx.x * 128;
    const int n0 = blockIdx.y * 256;
    const int kz = blockIdx.z;
    const bool txt = (m0 < S_TXTC);
    const float* A = g_O + (size_t)m0 * DIMK + kz * 1024;
    const float* W = (txt ? g_Wao : g_Wo) + (size_t)n0 * DIMK + kz * 1024;

    const int t = threadIdx.x;
    float acc[4][8][4];
#pragma unroll
    for (int i = 0; i < 4; i++)
#pragma unroll
        for (int j = 0; j < 8; j++)
#pragma unroll
            for (int c = 0; c < 4; c++) acc[i][j][c] = 0.f;

    gemm_tf32_main(A, W, su, acc, t, 32);

    const int lane = t & 31, wid = t >> 5;
    const int g = lane >> 2, t4 = lane & 3;
    const int wm = wid >> 2, wn = wid & 3;
    float* P = g_Pout[kz];
#pragma unroll
    for (int mt = 0; mt < 4; mt++) {
        int r0 = m0 + wm * 64 + mt * 16 + g;
#pragma unroll
        for (int nt = 0; nt < 8; nt++) {
            int c = n0 + wn * 64 + nt * 8 + t4 * 2;
            *(float2*)(P + (size_t)r0 * DIMK + c) =
                make_float2(acc[mt][nt][0], acc[mt][nt][1]);
            *(float2*)(P + (size_t)(r0 + 8) * DIMK + c) =
                make_float2(acc[mt][nt][2], acc[mt][nt][3]);
        }
    }
}

// ---------------- kernel 4b: combine partials + bias + scatter --------------
__global__ void combine_out_kernel(const float* __restrict__ b_img,
                                   const float* __restrict__ b_txt,
                                   float* __restrict__ out)
{
    const int N4 = S_TOT * DIMK / 4;
    for (int i = blockIdx.x * blockDim.x + threadIdx.x; i < N4;
         i += gridDim.x * blockDim.x) {
        int s = i / (DIMK / 4);
        int c = (i % (DIMK / 4)) * 4;
        const bool txt = (s < S_TXTC);
        float4 p0 = *(const float4*)(g_Pout[0] + (size_t)s * DIMK + c);
        float4 p1 = *(const float4*)(g_Pout[1] + (size_t)s * DIMK + c);
        float4 p2 = *(const float4*)(g_Pout[2] + (size_t)s * DIMK + c);
        float4 b = *(const float4*)((txt ? b_txt : b_img) + c);
        float4 v;
        v.x = p0.x + p1.x + p2.x + b.x;
        v.y = p0.y + p1.y + p2.y + b.y;
        v.z = p0.z + p1.z + p2.z + b.z;
        v.w = p0.w + p1.w + p2.w + b.w;
        int orow = txt ? (S_IMGC + s) : (s - S_TXTC);
        *(float4*)(out + (size_t)orow * DIMK + c) = v;
    }
}

// ====== flash v6 + KV-split 2: 128q-tile, two-tile S/softmax pipeline =======
#define KS_B   33792
#define VT_B   34816
#define VT_OFF (2 * KS_B)
#define PS_OFF (VT_OFF + 2 * VT_B)
#define FLASH_SMEM_BYTES (PS_OFF + VT_B)   // 172032

__device__ __forceinline__ void flash_issue_k(const float* __restrict__ Kg,
                                              uint32_t ksb, int t)
{
#pragma unroll
    for (int l = 0; l < 8; l++) {
        int idx = t + l * 256;
        int r = idx >> 5, c = idx & 31;
        cp16(ksb + (uint32_t)(r * 528 + c * 16), Kg + (size_t)r * HDIM + c * 4);
    }
}
__device__ __forceinline__ void flash_issue_v(const float* __restrict__ Vt,
                                              uint32_t vtb, int t)
{
#pragma unroll
    for (int l = 0; l < 8; l++) {
        int idx = t + l * 256;
        int r = idx >> 4, c = idx & 15;
        cp16(vtb + (uint32_t)(r * 272 + c * 16), Vt + (size_t)r * S_TOT + c * 4);
    }
}

__device__ __forceinline__ void flash_S(uint32_t ksb, const unsigned (&qf)[16][4],
                                        const uint32_t (&okk)[4], float (&sc)[8][4])
{
#pragma unroll
    for (int nt = 0; nt < 8; nt++)
#pragma unroll
        for (int c = 0; c < 4; c++) sc[nt][c] = 0.f;
#pragma unroll
    for (int ks = 0; ks < 16; ks++) {
        unsigned bf[8][2];
#pragma unroll
        for (int p = 0; p < 4; p++)
            LDSM4(bf[2 * p][0], bf[2 * p][1], bf[2 * p + 1][0],
                  bf[2 * p + 1][1], ksb + okk[p] + ks * 32);
#pragma unroll
        for (int nt = 0; nt < 8; nt++)
            mma8(sc[nt], qf[ks], bf[nt]);
    }
}

__global__ __launch_bounds__(256, 1) void flash_v6_kernel()
{
    extern __shared__ unsigned fsm[];
    const uint32_t su = smem_u32(fsm);

    const int qt = blockIdx.x, h = blockIdx.y, z = blockIdx.z;
    const int t = threadIdx.x, lane = t & 31, wid = t >> 5;
    const float* Kg0 = g_K + (size_t)h * S_TOT * HDIM + (size_t)z * 1280 * HDIM;
    const float* Vt0 = g_Vt + (size_t)h * HDIM * S_TOT + z * 1280;

    const int g = lane >> 2, t4 = lane & 3;
    const int qb = wid * 16;

    const int brow = (lane & 7) + ((lane >> 4) & 1) * 8;
    const int bcol = ((lane >> 3) & 1) * 4;
    const int parow = (lane & 7) + ((lane >> 3) & 1) * 8;
    const int pacol = (lane >> 4) * 4;
    uint32_t okk[4], ovv[8], opa;
#pragma unroll
    for (int p = 0; p < 4; p++) okk[p] = (uint32_t)((p * 16 + brow) * 132 + bcol) * 4;
#pragma unroll
    for (int p = 0; p < 8; p++) ovv[p] = (uint32_t)((p * 16 + brow) * 68 + bcol) * 4;
    opa = (uint32_t)((qb + parow) * 68 + pacol) * 4;

    flash_issue_k(Kg0, su, t);
    flash_issue_v(Vt0, su + VT_OFF, t);
    CP_COMMIT();

    unsigned qf[16][4];
    const float* Qg = g_Q + ((size_t)h * S_TOT + qt * 128) * HDIM;
#pragma unroll
    for (int ks = 0; ks < 16; ks++) {
        int k = ks * 8;
        qf[ks][0] = __float_as_uint(Qg[(size_t)(qb + g) * HDIM + k + t4]);
        qf[ks][1] = __float_as_uint(Qg[(size_t)(qb + g + 8) * HDIM + k + t4]);
        qf[ks][2] = __float_as_uint(Qg[(size_t)(qb + g) * HDIM + k + t4 + 4]);
        qf[ks][3] = __float_as_uint(Qg[(size_t)(qb + g + 8) * HDIM + k + t4 + 4]);
    }

    float o[16][4];
#pragma unroll
    for (int dt = 0; dt < 16; dt++)
#pragma unroll
        for (int c = 0; c < 4; c++) o[dt][c] = 0.f;
    float mrow[2] = {-1e30f, -1e30f}, lrow[2] = {0.f, 0.f};

    CP_WAIT0();
    __syncthreads();
    flash_issue_k(Kg0 + (size_t)64 * HDIM, su + KS_B, t);
    CP_COMMIT();

    float sc[8][4];
    flash_S(su, qf, okk, sc);

    const int NT = 1280 / 64;   // 20
    for (int kt = 0; kt < NT; kt++) {
        const int b = kt & 1;
        if (kt + 1 < NT) {
            flash_issue_v(Vt0 + (size_t)(kt + 1) * 64,
                          su + VT_OFF + (b ^ 1) * VT_B, t);
            CP_COMMIT();
            CP_WAIT1();
        } else {
            CP_WAIT0();
        }
        __syncthreads();
        if (kt + 2 < NT) {
            flash_issue_k(Kg0 + (size_t)(kt + 2) * 64 * HDIM, su + b * KS_B, t);
            CP_COMMIT();
        }
        float scn[8][4];
        if (kt + 1 < NT)
            flash_S(su + ((kt + 1) & 1) * KS_B, qf, okk, scn);

        float mx0 = -1e30f, mx1 = -1e30f;
#pragma unroll
        for (int nt = 0; nt < 8; nt++) {
            mx0 = fmaxf(mx0, fmaxf(sc[nt][0], sc[nt][1]));
            mx1 = fmaxf(mx1, fmaxf(sc[nt][2], sc[nt][3]));
        }
        mx0 = fmaxf(mx0, __shfl_xor_sync(0xffffffffu, mx0, 1));
        mx0 = fmaxf(mx0, __shfl_xor_sync(0xffffffffu, mx0, 2));
        mx1 = fmaxf(mx1, __shfl_xor_sync(0xffffffffu, mx1, 1));
        mx1 = fmaxf(mx1, __shfl_xor_sync(0xffffffffu, mx1, 2));
        float m0n = fmaxf(mrow[0], mx0), m1n = fmaxf(mrow[1], mx1);
        float a0 = ex2(mrow[0] - m0n), a1 = ex2(mrow[1] - m1n);
        mrow[0] = m0n; mrow[1] = m1n;

        float rs0 = 0.f, rs1 = 0.f;
#pragma unroll
        for (int nt = 0; nt < 8; nt++) {
            sc[nt][0] = ex2(sc[nt][0] - m0n);
            sc[nt][1] = ex2(sc[nt][1] - m0n);
            sc[nt][2] = ex2(sc[nt][2] - m1n);
            sc[nt][3] = ex2(sc[nt][3] - m1n);
            rs0 += sc[nt][0] + sc[nt][1];
            rs1 += sc[nt][2] + sc[nt][3];
        }
        rs0 += __shfl_xor_sync(0xffffffffu, rs0, 1);
        rs0 += __shfl_xor_sync(0xffffffffu, rs0, 2);
        rs1 += __shfl_xor_sync(0xffffffffu, rs1, 1);
        rs1 += __shfl_xor_sync(0xffffffffu, rs1, 2);
        lrow[0] = lrow[0] * a0 + rs0;
        lrow[1] = lrow[1] * a1 + rs1;

#pragma unroll
        for (int dt = 0; dt < 16; dt++) {
            o[dt][0] *= a0; o[dt][1] *= a0;
            o[dt][2] *= a1; o[dt][3] *= a1;
        }

        const uint32_t psb = su + PS_OFF;
#pragma unroll
        for (int nt = 0; nt < 8; nt++) {
            uint32_t pb = psb + (uint32_t)((qb + g) * 68 + nt * 8 + t4 * 2) * 4;
            STS32(pb,     f2tf(sc[nt][0]));
            STS32(pb + 4, f2tf(sc[nt][1]));
            STS32(pb + 8 * 68 * 4,     f2tf(sc[nt][2]));
            STS32(pb + 8 * 68 * 4 + 4, f2tf(sc[nt][3]));
        }
        __syncwarp();

        const uint32_t vtb = su + VT_OFF + b * VT_B;
#pragma unroll
        for (int ks = 0; ks < 8; ks++) {
            unsigned pa[4];
            LDSM4(pa[0], pa[1], pa[2], pa[3], psb + opa + ks * 32);
#pragma unroll
            for (int p = 0; p < 8; p++) {
                unsigned vf0[2], vf1[2];
                LDSM4(vf0[0], vf0[1], vf1[0], vf1[1], vtb + ovv[p] + ks * 32);
                mma8(o[2 * p], pa, vf0);
                mma8(o[2 * p + 1], pa, vf1);
            }
        }

        if (kt + 1 < NT) {
#pragma unroll
            for (int nt = 0; nt < 8; nt++)
#pragma unroll
                for (int c = 0; c < 4; c++) sc[nt][c] = scn[nt][c];
        }
        __syncthreads();
    }

    // epilogue: raw (unnormalized) partial O + per-row m/l for this half
    int s0 = qt * 128 + qb + g;
    float* dst0 = g_Fo[z] + (size_t)s0 * DIMK + h * HDIM;
    float* dst1 = dst0 + (size_t)8 * DIMK;
#pragma unroll
    for (int dt = 0; dt < 16; dt++) {
        int d = dt * 8 + t4 * 2;
        *(float2*)(dst0 + d) = make_float2(o[dt][0], o[dt][1]);
        *(float2*)(dst1 + d) = make_float2(o[dt][2], o[dt][3]);
    }
    if (t4 == 0) {
        g_Fm[z][h * S_TOT + s0] = mrow[0];
        g_Fm[z][h * S_TOT + s0 + 8] = mrow[1];
        g_Fl[z][h * S_TOT + s0] = lrow[0];
        g_Fl[z][h * S_TOT + s0 + 8] = lrow[1];
    }
}

// ---------------- combine the two KV halves -> rounded g_O ------------------
__global__ void combine_attn_kernel()
{
    const int N4 = S_TOT * DIMK / 4;
    for (int i = blockIdx.x * blockDim.x + threadIdx.x; i < N4;
         i += gridDim.x * blockDim.x) {
        int s = i / (DIMK / 4);
        int c = (i % (DIMK / 4)) * 4;
        int h = c >> 7;
        float m0 = g_Fm[0][h * S_TOT + s], m1 = g_Fm[1][h * S_TOT + s];
        float l0 = g_Fl[0][h * S_TOT + s], l1 = g_Fl[1][h * S_TOT + s];
        float m = fmaxf(m0, m1);
        float w0 = ex2(m0 - m), w1 = ex2(m1 - m);
        float inv = 1.0f / (l0 * w0 + l1 * w1);
        float4 a = *(const float4*)(g_Fo[0] + (size_t)s * DIMK + c);
        float4 b = *(const float4*)(g_Fo[1] + (size_t)s * DIMK + c);
        float4 v;
        v.x = rtf((a.x * w0 + b.x * w1) * inv);
        v.y = rtf((a.y * w0 + b.y * w1) * inv);
        v.z = rtf((a.z * w0 + b.z * w1) * inv);
        v.w = rtf((a.w * w0 + b.w * w1) * inv);
        *(float4*)(g_O + (size_t)s * DIMK + c) = v;
    }
}

// ---------------- launch ----------------------------------------------------
extern "C" void kernel_launch(void* const* d_in, const int* in_sizes, int n_in,
                              void* d_out, int out_size)
{
    const float* hid       = (const float*)d_in[0];
    const float* enc       = (const float*)d_in[1];
    const float* cosT      = (const float*)d_in[2];
    const float* sinT      = (const float*)d_in[3];
    const float* w_qkv     = (const float*)d_in[4];
    const float* b_qkv     = (const float*)d_in[5];
    const float* w_add     = (const float*)d_in[6];
    const float* b_add     = (const float*)d_in[7];
    const float* nq        = (const float*)d_in[8];
    const float* nk        = (const float*)d_in[9];
    const float* naq       = (const float*)d_in[10];
    const float* nak       = (const float*)d_in[11];
    const float* w_out     = (const float*)d_in[12];
    const float* b_out     = (const float*)d_in[13];
    const float* w_add_out = (const float*)d_in[14];
    const float* b_add_out = (const float*)d_in[15];
    float* out = (float*)d_out;

    static bool attr_done = false;
    if (!attr_done) {
        cudaFuncSetAttribute(gemm_qkv_kernel,
            cudaFuncAttributeMaxDynamicSharedMemorySize, GEMM_SMEM_BYTES);
        cudaFuncSetAttribute(gemm_out_kernel,
            cudaFuncAttributeMaxDynamicSharedMemorySize, GEMM_SMEM_BYTES);
        cudaFuncSetAttribute(flash_v6_kernel,
            cudaFuncAttributeMaxDynamicSharedMemorySize, FLASH_SMEM_BYTES);
        attr_done = true;
    }

    cvt_all_kernel<<<2048, 256>>>(w_qkv, w_add, w_out, w_add_out, enc, hid);

    gemm_qkv_kernel<<<dim3(S_TOT / 128, E3 / 256), 256, GEMM_SMEM_BYTES>>>(
        b_qkv, b_add, cosT, sinT, nq, nk, naq, nak);

    flash_v6_kernel<<<dim3(S_TOT / 128, NHEADS, 2), 256, FLASH_SMEM_BYTES>>>();

    combine_attn_kernel<<<2048, 256>>>();

    gemm_out_kernel<<<dim3(S_TOT / 128, DIMK / 256, 3), 256, GEMM_SMEM_BYTES>>>(out);

    combine_out_kernel<<<2048, 256>>>(b_out, b_add_out, out);
}